// round 3
// baseline (speedup 1.0000x reference)
#include <cuda_runtime.h>
#include <math.h>
#include <float.h>

// RepulsionLoss: B=8, N=4096, KNN=4, H=0.03
// Warp-coherent KNN: all 32 lanes scan candidates for the SAME query with a
// warp-uniform (replicated) top-5 list. Common path = 3 FMA + vote; insertions
// are rare, collective, and warp-uniform (no divergence at sync points).
// v = |p|^2 - 2 p.q (query's |q|^2 deferred); self lands in slot 0 and is
// dropped, matching the reference's top_k(5)-drop-first.

#define B_SZ     8
#define N_SZ     4096
#define THREADS  256
#define WARPS    (THREADS / 32)
#define QPW      4                      // queries per warp
#define QPB      (WARPS * QPW)          // 32 queries per block
#define TILE     2048
#define CHUNKS   (TILE / 32)            // 64 candidate chunks per tile
#define GROUPS   (N_SZ / QPB)           // 128 query-groups per batch
#define GRID_SZ  (B_SZ * GROUPS)        // 1024 blocks
#define H2       (0.03f * 0.03f)
#define FULL     0xffffffffu

__device__ float g_partial[GRID_SZ];

// Branch-free insert into sorted ascending 5-list, dropping the max.
__device__ __forceinline__ void ins5(float* d, float v) {
    float t;
    d[4] = fminf(d[4], v);
    t = fminf(d[3], d[4]); d[4] = fmaxf(d[3], d[4]); d[3] = t;
    t = fminf(d[2], d[3]); d[3] = fmaxf(d[2], d[3]); d[2] = t;
    t = fminf(d[1], d[2]); d[2] = fmaxf(d[1], d[2]); d[1] = t;
    t = fminf(d[0], d[1]); d[1] = fmaxf(d[0], d[1]); d[0] = t;
}

__global__ __launch_bounds__(THREADS)
void repulsion_knn_kernel(const float* __restrict__ pc) {
    __shared__ float4 spts[TILE];            // 32 KB: (x, y, z, |p|^2)
    __shared__ float  wsum[WARPS];

    const int tid  = threadIdx.x;
    const int warp = tid >> 5;
    const int lane = tid & 31;
    const int b    = blockIdx.x >> 7;                 // / GROUPS
    const int grp  = blockIdx.x & (GROUPS - 1);
    const int q0   = grp * QPB + warp * QPW;          // first query of this warp

    const float* __restrict__ batch = pc + (size_t)b * N_SZ * 3;

    float m2x[QPW], m2y[QPW], m2z[QPW], qsq[QPW];
    float d[QPW][5];
    #pragma unroll
    for (int qi = 0; qi < QPW; ++qi) {
        const int q = q0 + qi;
        float qx = batch[q * 3 + 0];
        float qy = batch[q * 3 + 1];
        float qz = batch[q * 3 + 2];
        m2x[qi] = -2.0f * qx; m2y[qi] = -2.0f * qy; m2z[qi] = -2.0f * qz;
        qsq[qi] = fmaf(qx, qx, fmaf(qy, qy, qz * qz));
        #pragma unroll
        for (int k = 0; k < 5; ++k) d[qi][k] = FLT_MAX;
    }

    for (int t0 = 0; t0 < N_SZ; t0 += TILE) {
        // Stage xyz (coalesced), then fill w = |p|^2.
        const float* __restrict__ src = batch + (size_t)t0 * 3;
        for (int e = tid; e < TILE * 3; e += THREADS) {
            int j = e / 3;
            int c = e - j * 3;
            reinterpret_cast<float*>(&spts[j])[c] = src[e];
        }
        __syncthreads();
        for (int j = tid; j < TILE; j += THREADS) {
            float4 p = spts[j];
            spts[j].w = fmaf(p.x, p.x, fmaf(p.y, p.y, p.z * p.z));
        }
        __syncthreads();

        for (int c = 0; c < CHUNKS; ++c) {
            float4 p = spts[c * 32 + lane];
            #pragma unroll
            for (int qi = 0; qi < QPW; ++qi) {
                float v = fmaf(p.z, m2z[qi], p.w);
                v = fmaf(p.y, m2y[qi], v);
                v = fmaf(p.x, m2x[qi], v);
                // Warp-uniform rare path: vote result identical on all lanes.
                if (__any_sync(FULL, v < d[qi][4])) {
                    unsigned bal = __ballot_sync(FULL, v < d[qi][4]);
                    while (bal) {
                        int   l  = __ffs(bal) - 1;
                        float vb = __shfl_sync(FULL, v, l);
                        ins5(d[qi], vb);            // replicated: stays uniform
                        bal &= bal - 1;
                        bal &= __ballot_sync(FULL, v < d[qi][4]);
                    }
                }
            }
        }
        __syncthreads();
    }

    // Loss for this warp's queries (values are warp-uniform).
    const float inv = -1.0f / H2;
    float acc = 0.0f;
    #pragma unroll
    for (int qi = 0; qi < QPW; ++qi) {
        #pragma unroll
        for (int k = 1; k < 5; ++k) {                 // drop slot 0 (self)
            float s = fmaxf(d[qi][k] + qsq[qi], 0.0f);
            acc -= s * expf(s * inv);
        }
    }
    if (lane == 0) wsum[warp] = acc;
    __syncthreads();
    if (tid == 0) {
        float s = 0.0f;
        #pragma unroll
        for (int w = 0; w < WARPS; ++w) s += wsum[w];
        g_partial[blockIdx.x] = s;
    }
}

__global__ void repulsion_final_reduce(float* __restrict__ out) {
    __shared__ float ws[GRID_SZ / 32];
    const int tid = threadIdx.x;              // 1024 threads
    float v = g_partial[tid];
    #pragma unroll
    for (int o = 16; o > 0; o >>= 1)
        v += __shfl_down_sync(FULL, v, o);
    if ((tid & 31) == 0) ws[tid >> 5] = v;
    __syncthreads();
    if (tid < 32) {
        float s = (tid < GRID_SZ / 32) ? ws[tid] : 0.0f;
        #pragma unroll
        for (int o = 16; o > 0; o >>= 1)
            s += __shfl_down_sync(FULL, s, o);
        if (tid == 0) out[0] = s;
    }
}

extern "C" void kernel_launch(void* const* d_in, const int* in_sizes, int n_in,
                              void* d_out, int out_size) {
    const float* pc = (const float*)d_in[0];
    repulsion_knn_kernel<<<GRID_SZ, THREADS>>>(pc);
    repulsion_final_reduce<<<1, GRID_SZ>>>((float*)d_out);
}

// round 4
// speedup vs baseline: 1.0458x; 1.0458x over previous
#include <cuda_runtime.h>
#include <math.h>
#include <float.h>

// RepulsionLoss: B=8, N=4096, KNN=4, H=0.03
// Branchless per-thread top-5 selection (9 FMNMX/pair, alu-pipe bound).
// v = |p|^2 - 2 p.q (|q|^2 deferred); self is the strict minimum -> slot 0,
// dropped, matching the reference's top_k(KNN+1)-drop-first.

#define B_SZ     8
#define N_SZ     4096
#define THREADS  128
#define QPB      16                    // queries per block
#define SPLIT    8                     // candidate splits per query
#define TILE     512                   // candidates staged per pass
#define NTILES   (N_SZ / TILE)         // 8
#define SEG      (TILE / SPLIT)        // 64 iterations per thread per tile
#define GROUPS   (N_SZ / QPB)          // 256 query-groups per batch
#define GRID_SZ  (B_SZ * GROUPS)       // 2048 blocks
#define H2       (0.03f * 0.03f)
#define FULL     0xffffffffu

__device__ float4 g_aug[B_SZ * N_SZ];      // (x, y, z, |p|^2)
__device__ float  g_partial[GRID_SZ];
__device__ int    g_done;                   // zero-init; self-resetting

// Branch-free insert of v into sorted ascending 5-list, dropping the max.
__device__ __forceinline__ void ins5(float& d0, float& d1, float& d2,
                                     float& d3, float& d4, float v) {
    float t;
    d4 = fminf(d4, v);
    t = fminf(d3, d4); d4 = fmaxf(d3, d4); d3 = t;
    t = fminf(d2, d3); d3 = fmaxf(d2, d3); d2 = t;
    t = fminf(d1, d2); d2 = fmaxf(d1, d2); d1 = t;
    t = fminf(d0, d1); d1 = fmaxf(d0, d1); d0 = t;
}

__global__ __launch_bounds__(256)
void augment_kernel(const float* __restrict__ pc) {
    int i = blockIdx.x * 256 + threadIdx.x;          // 0 .. B*N-1
    float x = pc[i * 3 + 0];
    float y = pc[i * 3 + 1];
    float z = pc[i * 3 + 2];
    g_aug[i] = make_float4(x, y, z, fmaf(x, x, fmaf(y, y, z * z)));
}

__global__ __launch_bounds__(THREADS, 14)
void repulsion_knn_kernel(const float* __restrict__ pc, float* __restrict__ out) {
    __shared__ float4 spts[TILE];                    // 8 KB
    __shared__ float  mbuf[THREADS][5];              // 2.5 KB
    __shared__ float  wsum[THREADS / 32];
    __shared__ int    is_last;

    const int tid   = threadIdx.x;
    const int split = tid & (SPLIT - 1);
    const int ql    = tid >> 3;                      // 0..15
    const int b     = blockIdx.x >> 8;               // / GROUPS
    const int grp   = blockIdx.x & (GROUPS - 1);
    const int q     = grp * QPB + ql;

    const float*  __restrict__ batch = pc + (size_t)b * N_SZ * 3;
    const float4* __restrict__ aug   = g_aug + b * N_SZ;

    const float qx = batch[q * 3 + 0];
    const float qy = batch[q * 3 + 1];
    const float qz = batch[q * 3 + 2];
    const float m2x = -2.0f * qx, m2y = -2.0f * qy, m2z = -2.0f * qz;
    const float qsq = fmaf(qx, qx, fmaf(qy, qy, qz * qz));

    float d0 = FLT_MAX, d1 = FLT_MAX, d2 = FLT_MAX, d3 = FLT_MAX, d4 = FLT_MAX;

    for (int t0 = 0; t0 < NTILES; ++t0) {
        const float4* __restrict__ src = aug + t0 * TILE;
        #pragma unroll
        for (int j = tid; j < TILE; j += THREADS) spts[j] = src[j];
        __syncthreads();

        // Interleaved split: the 8 splits of a warp read 8 contiguous float4s
        // -> one conflict-free 128-B LDS wavefront per iteration.
        #pragma unroll 4
        for (int i = 0; i < SEG; ++i) {
            float4 p = spts[i * SPLIT + split];
            float v = fmaf(p.x, m2x, fmaf(p.y, m2y, fmaf(p.z, m2z, p.w)));
            ins5(d0, d1, d2, d3, d4, v);
        }
        __syncthreads();
    }

    // Merge the 8 per-split lists of each query.
    mbuf[tid][0] = d0; mbuf[tid][1] = d1; mbuf[tid][2] = d2;
    mbuf[tid][3] = d3; mbuf[tid][4] = d4;
    __syncthreads();

    float loss = 0.0f;
    if (split == 0) {
        #pragma unroll
        for (int s = 1; s < SPLIT; ++s) {
            const float* o = mbuf[tid + s];
            #pragma unroll
            for (int k = 0; k < 5; ++k) ins5(d0, d1, d2, d3, d4, o[k]);
        }
        const float inv = -1.0f / H2;
        float s1 = fmaxf(d1 + qsq, 0.0f);
        float s2 = fmaxf(d2 + qsq, 0.0f);
        float s3 = fmaxf(d3 + qsq, 0.0f);
        float s4 = fmaxf(d4 + qsq, 0.0f);
        loss = -s1 * expf(s1 * inv) - s2 * expf(s2 * inv)
             - s3 * expf(s3 * inv) - s4 * expf(s4 * inv);
    }

    // Deterministic in-block reduction.
    #pragma unroll
    for (int o = 16; o > 0; o >>= 1)
        loss += __shfl_down_sync(FULL, loss, o);
    if ((tid & 31) == 0) wsum[tid >> 5] = loss;
    __syncthreads();

    if (tid == 0) {
        float s = wsum[0] + wsum[1] + wsum[2] + wsum[3];
        g_partial[blockIdx.x] = s;
        __threadfence();
        int n = atomicAdd(&g_done, 1);
        is_last = (n == GRID_SZ - 1);
    }
    __syncthreads();

    // Last block performs the (fixed-order, deterministic) final reduction.
    if (is_last) {
        __threadfence();
        float v = 0.0f;
        #pragma unroll
        for (int i = tid; i < GRID_SZ; i += THREADS) v += g_partial[i];
        #pragma unroll
        for (int o = 16; o > 0; o >>= 1)
            v += __shfl_down_sync(FULL, v, o);
        if ((tid & 31) == 0) wsum[tid >> 5] = v;
        __syncthreads();
        if (tid == 0) {
            out[0] = wsum[0] + wsum[1] + wsum[2] + wsum[3];
            g_done = 0;                       // reset for next graph replay
        }
    }
}

extern "C" void kernel_launch(void* const* d_in, const int* in_sizes, int n_in,
                              void* d_out, int out_size) {
    const float* pc = (const float*)d_in[0];
    augment_kernel<<<(B_SZ * N_SZ) / 256, 256>>>(pc);
    repulsion_knn_kernel<<<GRID_SZ, THREADS>>>(pc, (float*)d_out);
}

// round 5
// speedup vs baseline: 1.4323x; 1.3695x over previous
#include <cuda_runtime.h>
#include <math.h>
#include <float.h>

// RepulsionLoss: B=8, N=4096, KNN=4, H=0.03
// Batched branch-free top-5: per 4 candidates, sort-4 (5 CE) + bitonic
// min-trick (4 min) + unimodal merge-5 (5 CE) = 6 alu ops/pair (was 9).
// Each thread serves 2 queries per candidate load; lanes 0-15/16-31 mirror
// LDS addresses (broadcast) -> 4 B/pair smem traffic.
// v = |p|^2 - 2 p.q (|q|^2 deferred); self is the strict global min -> ends
// in slot 0 after the final merge and is dropped (ref: top_k(5)-drop-first).

#define B_SZ     8
#define N_SZ     4096
#define THREADS  128
#define SLOTS    8                     // query-pair slots per block
#define SPLIT    16                    // candidate splits per query
#define QPB      (SLOTS * 2)           // 16 queries per block
#define TILE     512                   // candidates staged per pass (8 KB)
#define NTILES   (N_SZ / TILE)         // 8
#define BPT      8                     // batches of 4 per thread per tile
#define GROUPS   (N_SZ / QPB)          // 256
#define GRID_SZ  (B_SZ * GROUPS)       // 2048 blocks
#define H2       (0.03f * 0.03f)
#define FULL     0xffffffffu

__device__ float4 g_aug[B_SZ * N_SZ];      // (x, y, z, |p|^2)
__device__ float  g_partial[GRID_SZ];
__device__ int    g_done;                   // zero-init; self-resetting

#define CE(x, y) { float t_ = fminf((x), (y)); (y) = fmaxf((x), (y)); (x) = t_; }

// Classic 9-op insert (used only in the rare merge phases).
__device__ __forceinline__ void ins5(float& d0, float& d1, float& d2,
                                     float& d3, float& d4, float v) {
    d4 = fminf(d4, v);
    CE(d3, d4) CE(d2, d3) CE(d1, d2) CE(d0, d1)
}

__global__ __launch_bounds__(256)
void augment_kernel(const float* __restrict__ pc) {
    int i = blockIdx.x * 256 + threadIdx.x;
    float x = pc[i * 3 + 0];
    float y = pc[i * 3 + 1];
    float z = pc[i * 3 + 2];
    g_aug[i] = make_float4(x, y, z, fmaf(x, x, fmaf(y, y, z * z)));
}

__global__ __launch_bounds__(THREADS)
void repulsion_knn_kernel(const float* __restrict__ pc, float* __restrict__ out) {
    __shared__ float4 spts[TILE];                 // 8 KB
    __shared__ float  mbufA[THREADS][5];          // per-split lists, query A
    __shared__ float  mbufB[THREADS][5];          // per-split lists, query B
    __shared__ float  wsum[SLOTS];
    __shared__ int    is_last;

    const int tid   = threadIdx.x;
    const int split = tid & (SPLIT - 1);
    const int slot  = tid >> 4;                   // 0..7
    const int b     = blockIdx.x >> 8;            // / GROUPS
    const int grp   = blockIdx.x & (GROUPS - 1);
    const int qa    = grp * QPB + slot * 2;
    const int qb    = qa + 1;

    const float*  __restrict__ batch = pc + (size_t)b * N_SZ * 3;
    const float4* __restrict__ aug   = g_aug + b * N_SZ;

    const float axm = -2.0f * batch[qa * 3 + 0];
    const float aym = -2.0f * batch[qa * 3 + 1];
    const float azm = -2.0f * batch[qa * 3 + 2];
    const float bxm = -2.0f * batch[qb * 3 + 0];
    const float bym = -2.0f * batch[qb * 3 + 1];
    const float bzm = -2.0f * batch[qb * 3 + 2];
    const float aqs = 0.25f * fmaf(axm, axm, fmaf(aym, aym, azm * azm));
    const float bqs = 0.25f * fmaf(bxm, bxm, fmaf(bym, bym, bzm * bzm));

    float a0 = FLT_MAX, a1 = FLT_MAX, a2 = FLT_MAX, a3 = FLT_MAX, a4 = FLT_MAX;
    float b0 = FLT_MAX, b1 = FLT_MAX, b2 = FLT_MAX, b3 = FLT_MAX, b4 = FLT_MAX;

    for (int t0 = 0; t0 < NTILES; ++t0) {
        const float4* __restrict__ src = aug + t0 * TILE;
        #pragma unroll
        for (int j = tid; j < TILE; j += THREADS) spts[j] = src[j];
        __syncthreads();

        #pragma unroll 4
        for (int k = 0; k < BPT; ++k) {
            // Lanes l and l+16 read identical addresses -> LDS broadcast;
            // lanes 0-15 cover 16 contiguous float4s -> conflict-free.
            float4 p0 = spts[(k * 4 + 0) * SPLIT + split];
            float4 p1 = spts[(k * 4 + 1) * SPLIT + split];
            float4 p2 = spts[(k * 4 + 2) * SPLIT + split];
            float4 p3 = spts[(k * 4 + 3) * SPLIT + split];

            // ---- query A ----
            {
                float va = fmaf(p0.x, axm, fmaf(p0.y, aym, fmaf(p0.z, azm, p0.w)));
                float vb = fmaf(p1.x, axm, fmaf(p1.y, aym, fmaf(p1.z, azm, p1.w)));
                float vc = fmaf(p2.x, axm, fmaf(p2.y, aym, fmaf(p2.z, azm, p2.w)));
                float vd = fmaf(p3.x, axm, fmaf(p3.y, aym, fmaf(p3.z, azm, p3.w)));
                CE(va, vb) CE(vc, vd) CE(va, vc) CE(vb, vd) CE(vb, vc)
                a1 = fminf(a1, vd); a2 = fminf(a2, vc);
                a3 = fminf(a3, vb); a4 = fminf(a4, va);
                CE(a0, a4) CE(a1, a3) CE(a2, a4) CE(a1, a2) CE(a3, a4)
            }
            // ---- query B ----
            {
                float va = fmaf(p0.x, bxm, fmaf(p0.y, bym, fmaf(p0.z, bzm, p0.w)));
                float vb = fmaf(p1.x, bxm, fmaf(p1.y, bym, fmaf(p1.z, bzm, p1.w)));
                float vc = fmaf(p2.x, bxm, fmaf(p2.y, bym, fmaf(p2.z, bzm, p2.w)));
                float vd = fmaf(p3.x, bxm, fmaf(p3.y, bym, fmaf(p3.z, bzm, p3.w)));
                CE(va, vb) CE(vc, vd) CE(va, vc) CE(vb, vd) CE(vb, vc)
                b1 = fminf(b1, vd); b2 = fminf(b2, vc);
                b3 = fminf(b3, vb); b4 = fminf(b4, va);
                CE(b0, b4) CE(b1, b3) CE(b2, b4) CE(b1, b2) CE(b3, b4)
            }
        }
        __syncthreads();
    }

    // Tree-merge the 16 per-split lists of each query.
    mbufA[tid][0] = a0; mbufA[tid][1] = a1; mbufA[tid][2] = a2;
    mbufA[tid][3] = a3; mbufA[tid][4] = a4;
    mbufB[tid][0] = b0; mbufB[tid][1] = b1; mbufB[tid][2] = b2;
    mbufB[tid][3] = b3; mbufB[tid][4] = b4;

    #pragma unroll
    for (int step = SPLIT / 2; step >= 1; step >>= 1) {
        __syncthreads();
        if (split < step) {
            const float* oa = mbufA[tid + step];
            const float* ob = mbufB[tid + step];
            #pragma unroll
            for (int k = 0; k < 5; ++k) {
                ins5(a0, a1, a2, a3, a4, oa[k]);
                ins5(b0, b1, b2, b3, b4, ob[k]);
            }
            mbufA[tid][0] = a0; mbufA[tid][1] = a1; mbufA[tid][2] = a2;
            mbufA[tid][3] = a3; mbufA[tid][4] = a4;
            mbufB[tid][0] = b0; mbufB[tid][1] = b1; mbufB[tid][2] = b2;
            mbufB[tid][3] = b3; mbufB[tid][4] = b4;
        }
    }
    __syncthreads();

    if (split == 0) {
        const float inv = -1.0f / H2;
        float acc = 0.0f;
        float s;
        s = fmaxf(a1 + aqs, 0.0f); acc -= s * expf(s * inv);
        s = fmaxf(a2 + aqs, 0.0f); acc -= s * expf(s * inv);
        s = fmaxf(a3 + aqs, 0.0f); acc -= s * expf(s * inv);
        s = fmaxf(a4 + aqs, 0.0f); acc -= s * expf(s * inv);
        s = fmaxf(b1 + bqs, 0.0f); acc -= s * expf(s * inv);
        s = fmaxf(b2 + bqs, 0.0f); acc -= s * expf(s * inv);
        s = fmaxf(b3 + bqs, 0.0f); acc -= s * expf(s * inv);
        s = fmaxf(b4 + bqs, 0.0f); acc -= s * expf(s * inv);
        wsum[slot] = acc;
    }
    __syncthreads();

    if (tid == 0) {
        float sacc = 0.0f;
        #pragma unroll
        for (int w = 0; w < SLOTS; ++w) sacc += wsum[w];
        g_partial[blockIdx.x] = sacc;
        __threadfence();
        int n = atomicAdd(&g_done, 1);
        is_last = (n == GRID_SZ - 1);
    }
    __syncthreads();

    if (is_last) {
        __threadfence();
        float v = 0.0f;
        #pragma unroll
        for (int i = tid; i < GRID_SZ; i += THREADS) v += g_partial[i];
        #pragma unroll
        for (int o = 16; o > 0; o >>= 1)
            v += __shfl_down_sync(FULL, v, o);
        __shared__ float fsum[THREADS / 32];
        if ((tid & 31) == 0) fsum[tid >> 5] = v;
        __syncthreads();
        if (tid == 0) {
            out[0] = fsum[0] + fsum[1] + fsum[2] + fsum[3];
            g_done = 0;                       // reset for next graph replay
        }
    }
}

extern "C" void kernel_launch(void* const* d_in, const int* in_sizes, int n_in,
                              void* d_out, int out_size) {
    const float* pc = (const float*)d_in[0];
    augment_kernel<<<(B_SZ * N_SZ) / 256, 256>>>(pc);
    repulsion_knn_kernel<<<GRID_SZ, THREADS>>>(pc, (float*)d_out);
}